// round 6
// baseline (speedup 1.0000x reference)
#include <cuda_runtime.h>
#include <math.h>

#define NN 2048
#define AA 100
#define BB 64
#define NTILE 32           // NN / BB (FW band grid)
#define OUT_SUM (NN*AA)
#define OUT_G   (NN*AA+1)

// Scratch (static __device__ arrays — no allocation)
__device__ float d_dist[NN*NN];       // 16 MB distance matrix
__device__ int   d_anchors[AA];
__device__ float d_weighted[NN*AA];
__device__ float d_xx[NN];
__device__ float d_rowsum[NN];

__device__ __forceinline__ float finf() { return __int_as_float(0x7f800000); }

// ---------------------------------------------------------------------------
// Build w: adj = motif * nw[i] (row-scaled), w = min(f(adj), f(adj^T)), diag 0
// ---------------------------------------------------------------------------
__global__ void __launch_bounds__(256) k_build_w(const float* __restrict__ m,
                                                 const float* __restrict__ nw) {
    __shared__ float sT[32][33];
    int bi = blockIdx.y, bj = blockIdx.x;
    int tx = threadIdx.x & 31;
    int ty = threadIdx.x >> 5;
    #pragma unroll
    for (int rr = ty; rr < 32; rr += 8)
        sT[rr][tx] = m[(bj*32 + rr)*NN + bi*32 + tx];
    __syncthreads();
    #pragma unroll
    for (int rr = ty; rr < 32; rr += 8) {
        int i = bi*32 + rr;
        int j = bj*32 + tx;
        float a = m[i*NN + j] * nw[i];
        float b = sT[tx][rr] * nw[j];
        float wa = a > 0.f ? a : finf();
        float wb = b > 0.f ? b : finf();
        float w = fminf(wa, wb);
        if (i == j) w = 0.f;
        d_dist[i*NN + j] = w;
    }
}

// ---------------------------------------------------------------------------
// Fused phase1+2 (band k): all 64 blocks redundantly close pivot (k,k) in
// smem, then bid<32 updates row panel (k,o), bid>=32 col panel (o,k).
// ---------------------------------------------------------------------------
__global__ void __launch_bounds__(256) fw_p12(int k) {
    __shared__ float Ps[BB][BB + 4];
    __shared__ float B1[BB][BB + 4];
    int tid = threadIdx.x;
    const int kB = k * BB;
    const int pbase = kB * NN + kB;

    #pragma unroll
    for (int e = tid; e < BB * BB; e += 256)
        Ps[e >> 6][e & 63] = d_dist[pbase + (e >> 6) * NN + (e & 63)];
    __syncthreads();

    int r  = tid >> 2;
    int c0 = (tid & 3) << 4;
    float cur[16];
    #pragma unroll
    for (int x = 0; x < 16; x++) cur[x] = Ps[r][c0 + x];

    for (int kk = 0; kk < BB; kk++) {
        float a = Ps[r][kk];
        float bv[16];
        #pragma unroll
        for (int q = 0; q < 4; q++) {
            float4 v = *(const float4*)&Ps[kk][c0 + q * 4];
            bv[q*4+0] = v.x; bv[q*4+1] = v.y; bv[q*4+2] = v.z; bv[q*4+3] = v.w;
        }
        #pragma unroll
        for (int x = 0; x < 16; x++)
            cur[x] = fminf(cur[x], a + bv[x]);
        #pragma unroll
        for (int q = 0; q < 4; q++)
            *(float4*)&Ps[r][c0 + q * 4] =
                make_float4(cur[q*4+0], cur[q*4+1], cur[q*4+2], cur[q*4+3]);
        __syncthreads();
    }

    int bid = blockIdx.x;
    int o = bid & 31;
    int tx = tid & 15, ty = tid >> 4;
    int rr0 = ty << 2, cc0 = tx << 2;
    float acc[4][4];
    #pragma unroll
    for (int a = 0; a < 4; a++)
        #pragma unroll
        for (int b = 0; b < 4; b++) acc[a][b] = finf();

    if (bid < 32) {
        #pragma unroll
        for (int x = 0; x < 16; x++) B1[c0 + x][r] = cur[x];   // P*^T
        #pragma unroll
        for (int e = tid; e < BB * BB; e += 256)
            Ps[e >> 6][e & 63] = d_dist[(kB + (e >> 6)) * NN + o * BB + (e & 63)];
        __syncthreads();
        #pragma unroll 4
        for (int p = 0; p < BB; p++) {
            float4 a4 = *(const float4*)&B1[p][rr0];
            float4 b4 = *(const float4*)&Ps[p][cc0];
            float av[4] = {a4.x, a4.y, a4.z, a4.w};
            float bv[4] = {b4.x, b4.y, b4.z, b4.w};
            #pragma unroll
            for (int a = 0; a < 4; a++)
                #pragma unroll
                for (int b = 0; b < 4; b++)
                    acc[a][b] = fminf(acc[a][b], av[a] + bv[b]);
        }
        #pragma unroll
        for (int a = 0; a < 4; a++)
            *(float4*)&d_dist[(kB + rr0 + a) * NN + o * BB + cc0] =
                make_float4(acc[a][0], acc[a][1], acc[a][2], acc[a][3]);
    } else {
        #pragma unroll
        for (int e = tid; e < BB * BB; e += 256) {
            int ii = e >> 6, p = e & 63;
            B1[p][ii] = d_dist[(o * BB + ii) * NN + kB + p];
        }
        __syncthreads();
        #pragma unroll 4
        for (int p = 0; p < BB; p++) {
            float4 a4 = *(const float4*)&B1[p][rr0];
            float4 b4 = *(const float4*)&Ps[p][cc0];
            float av[4] = {a4.x, a4.y, a4.z, a4.w};
            float bv[4] = {b4.x, b4.y, b4.z, b4.w};
            #pragma unroll
            for (int a = 0; a < 4; a++)
                #pragma unroll
                for (int b = 0; b < 4; b++)
                    acc[a][b] = fminf(acc[a][b], av[a] + bv[b]);
        }
        #pragma unroll
        for (int a = 0; a < 4; a++)
            *(float4*)&d_dist[(o * BB + rr0 + a) * NN + kB + cc0] =
                make_float4(acc[a][0], acc[a][1], acc[a][2], acc[a][3]);
    }
}

// ---------------------------------------------------------------------------
// Critical phase3 slice for round k: update ONLY band k+1 (row tiles (k+1,o)
// and col tiles (o,k+1)). C = min(C, A(.,k) (+,min) B(k,.)).
// ---------------------------------------------------------------------------
__global__ void __launch_bounds__(256) fw_crit(int k) {
    int bid = blockIdx.x;
    int k1 = k + 1;
    int o = bid & 31;
    bool rowTile = bid < 32;
    if (!rowTile && o == k1) return;       // avoid duplicate (k+1,k+1)
    int ti = rowTile ? k1 : o;
    int tj = rowTile ? o  : k1;
    __shared__ float AsT[BB][BB + 4];
    __shared__ float Bs [BB][BB + 4];
    int tid = threadIdx.x;
    const int kB = k * BB;
    const int abase = (ti * BB) * NN + kB;
    const int bbase = kB * NN + tj * BB;
    #pragma unroll
    for (int e = tid; e < BB * BB; e += 256) {
        int rr = e >> 6, cc = e & 63;
        AsT[cc][rr] = d_dist[abase + rr * NN + cc];
        Bs [rr][cc] = d_dist[bbase + rr * NN + cc];
    }
    int tx = tid & 15, ty = tid >> 4;
    int r0 = ty << 2, c0 = tx << 2;
    const int cbase = (ti * BB + r0) * NN + tj * BB + c0;
    float acc[4][4];
    #pragma unroll
    for (int a = 0; a < 4; a++) {
        float4 v = *(const float4*)&d_dist[cbase + a * NN];
        acc[a][0] = v.x; acc[a][1] = v.y; acc[a][2] = v.z; acc[a][3] = v.w;
    }
    __syncthreads();
    #pragma unroll 4
    for (int p = 0; p < BB; p++) {
        float4 a4 = *(const float4*)&AsT[p][r0];
        float4 b4 = *(const float4*)&Bs[p][c0];
        float av[4] = {a4.x, a4.y, a4.z, a4.w};
        float bv[4] = {b4.x, b4.y, b4.z, b4.w};
        #pragma unroll
        for (int a = 0; a < 4; a++)
            #pragma unroll
            for (int b = 0; b < 4; b++)
                acc[a][b] = fminf(acc[a][b], av[a] + bv[b]);
    }
    #pragma unroll
    for (int a = 0; a < 4; a++)
        *(float4*)&d_dist[cbase + a * NN] =
            make_float4(acc[a][0], acc[a][1], acc[a][2], acc[a][3]);
}

// ---------------------------------------------------------------------------
// Bulk phase3: 128x128 C tiles, K=64 panel, 8x8 microtile. Stores MASKED in
// band `mk` (= k+1), owned by fw_crit this round. mk>=32 => no masking.
// ---------------------------------------------------------------------------
#define ASTR 132
__global__ void __launch_bounds__(256, 2) fw_rest(int k, int mk) {
    extern __shared__ float sm[];
    float* AsT = sm;                    // [64][ASTR]
    float* Bs  = sm + BB * ASTR;        // [64][128]
    int tid = threadIdx.x;
    int bx = blockIdx.x, by = blockIdx.y;
    const int kB = k * BB;

    #pragma unroll
    for (int e = tid; e < 128 * 64; e += 256) {
        int rr = e >> 6, p = e & 63;
        AsT[p * ASTR + rr] = d_dist[(by * 128 + rr) * NN + kB + p];
    }
    #pragma unroll
    for (int e = tid; e < 64 * 128; e += 256) {
        int p = e >> 7, j = e & 127;
        Bs[p * 128 + j] = d_dist[(kB + p) * NN + bx * 128 + j];
    }

    int tx = tid & 15, ty = tid >> 4;
    int r0 = ty << 3, c0 = tx << 3;
    const int cbase = (by * 128 + r0) * NN + bx * 128 + c0;
    float acc[8][8];
    #pragma unroll
    for (int a = 0; a < 8; a++) {
        float4 v0 = *(const float4*)&d_dist[cbase + a * NN];
        float4 v1 = *(const float4*)&d_dist[cbase + a * NN + 4];
        acc[a][0] = v0.x; acc[a][1] = v0.y; acc[a][2] = v0.z; acc[a][3] = v0.w;
        acc[a][4] = v1.x; acc[a][5] = v1.y; acc[a][6] = v1.z; acc[a][7] = v1.w;
    }
    __syncthreads();

    #pragma unroll 4
    for (int p = 0; p < BB; p++) {
        float4 a0 = *(const float4*)&AsT[p * ASTR + r0];
        float4 a1 = *(const float4*)&AsT[p * ASTR + r0 + 4];
        float4 b0 = *(const float4*)&Bs[p * 128 + c0];
        float4 b1 = *(const float4*)&Bs[p * 128 + c0 + 4];
        float av[8] = {a0.x, a0.y, a0.z, a0.w, a1.x, a1.y, a1.z, a1.w};
        float bv[8] = {b0.x, b0.y, b0.z, b0.w, b1.x, b1.y, b1.z, b1.w};
        #pragma unroll
        for (int a = 0; a < 8; a++)
            #pragma unroll
            for (int b = 0; b < 8; b++)
                acc[a][b] = fminf(acc[a][b], av[a] + bv[b]);
    }

    bool colOK = ((bx * 128 + c0) >> 6) != mk;
    #pragma unroll
    for (int a = 0; a < 8; a++) {
        bool rowOK = ((by * 128 + r0 + a) >> 6) != mk;
        if (rowOK & colOK) {
            *(float4*)&d_dist[cbase + a * NN] =
                make_float4(acc[a][0], acc[a][1], acc[a][2], acc[a][3]);
            *(float4*)&d_dist[cbase + a * NN + 4] =
                make_float4(acc[a][4], acc[a][5], acc[a][6], acc[a][7]);
        }
    }
}

// ---------------------------------------------------------------------------
// Anchors: exact stable argsort(-nw)[:100] via rank counting
// ---------------------------------------------------------------------------
__global__ void k_anchors(const float* __restrict__ nw) {
    __shared__ float s[NN];
    int tid = threadIdx.x;
    for (int e = tid; e < NN; e += 256) s[e] = nw[e];
    __syncthreads();
    int i = blockIdx.x * 256 + tid;
    float v = s[i];
    int rank = 0;
    for (int j = 0; j < NN; j++) {
        float u = s[j];
        rank += (u > v) || (u == v && j < i);
    }
    if (rank < AA) d_anchors[rank] = i;
}

// ---------------------------------------------------------------------------
__global__ void k_gather(const float* __restrict__ wm, float* __restrict__ out) {
    __shared__ int anc[AA];
    __shared__ float r1[128], r2[128];
    int i = blockIdx.x, tid = threadIdx.x;
    if (tid < AA) anc[tid] = d_anchors[tid];
    __syncthreads();
    float cv = 0.f, wsq = 0.f;
    if (tid < AA) {
        float v = d_dist[i * NN + anc[tid]];
        if (v > 3.0e38f) v = 100.f;
        out[i * AA + tid] = v;
        float w = wm[i * AA + tid] * v;
        d_weighted[i * AA + tid] = w;
        cv = v; wsq = w * w;
    }
    r1[tid] = cv; r2[tid] = wsq;
    __syncthreads();
    for (int st = 64; st > 0; st >>= 1) {
        if (tid < st) { r1[tid] += r1[tid + st]; r2[tid] += r2[tid + st]; }
        __syncthreads();
    }
    if (tid == 0) { d_rowsum[i] = r1[0]; d_xx[i] = r2[0]; }
}

__global__ void k_finalize(float* __restrict__ out) {
    __shared__ float red[256];
    int tid = threadIdx.x;
    float s = 0.f;
    for (int e = tid; e < NN; e += 256) s += d_rowsum[e];
    red[tid] = s;
    __syncthreads();
    for (int st = 128; st > 0; st >>= 1) {
        if (tid < st) red[tid] += red[tid + st];
        __syncthreads();
    }
    if (tid == 0) out[OUT_SUM] = (red[0] - 100.f * NN) / ((float)NN * AA);
}

// ---------------------------------------------------------------------------
__global__ void __launch_bounds__(256) k_graph(const float* __restrict__ sigma_p,
                                               float* __restrict__ out) {
    __shared__ float WiT[32][BB + 4];
    __shared__ float WjT[32][BB + 4];
    int bx = blockIdx.x, by = blockIdx.y;
    int tid = threadIdx.x, tx = tid & 15, ty = tid >> 4;
    int r0 = ty << 2, c0 = tx << 2;
    float acc[4][4] = {};
    for (int k0 = 0; k0 < 128; k0 += 32) {
        for (int e = tid; e < BB * 32; e += 256) {
            int rr = e >> 5, kc = e & 31;
            int kg = k0 + kc;
            float wi = 0.f, wj = 0.f;
            if (kg < AA) {
                wi = d_weighted[(by * BB + rr) * AA + kg];
                wj = d_weighted[(bx * BB + rr) * AA + kg];
            }
            WiT[kc][rr] = wi; WjT[kc][rr] = wj;
        }
        __syncthreads();
        #pragma unroll
        for (int kc = 0; kc < 32; kc++) {
            float4 a4 = *(const float4*)&WiT[kc][r0];
            float4 b4 = *(const float4*)&WjT[kc][c0];
            float av[4] = {a4.x, a4.y, a4.z, a4.w};
            float bv[4] = {b4.x, b4.y, b4.z, b4.w};
            #pragma unroll
            for (int a = 0; a < 4; a++)
                #pragma unroll
                for (int b = 0; b < 4; b++)
                    acc[a][b] += av[a] * bv[b];
        }
        __syncthreads();
    }
    float sg = *sigma_p;
    float inv2 = 0.5f / (sg * sg);
    float xi[4], xj[4];
    #pragma unroll
    for (int a = 0; a < 4; a++) xi[a] = d_xx[by * BB + r0 + a];
    #pragma unroll
    for (int b = 0; b < 4; b++) xj[b] = d_xx[bx * BB + c0 + b];
    #pragma unroll
    for (int a = 0; a < 4; a++) {
        int i = by * BB + r0 + a;
        #pragma unroll
        for (int b = 0; b < 4; b++) {
            int j = bx * BB + c0 + b;
            float sq = xi[a] + xj[b] - 2.f * acc[a][b];
            sq = fmaxf(sq, 0.f);
            out[OUT_G + i * NN + j] = expf(-(sq * sq) * inv2);
        }
    }
}

// ---------------------------------------------------------------------------
extern "C" void kernel_launch(void* const* d_in, const int* in_sizes, int n_in,
                              void* d_out, int out_size) {
    const float* m  = (const float*)d_in[0];
    const float* nw = (const float*)d_in[1];
    const float* wm = (const float*)d_in[2];
    const float* sg = (const float*)d_in[3];
    float* out = (float*)d_out;

    // One-time host objects, created on the first (uncaptured) correctness
    // call. If creation fails for any reason, fall back to single-stream
    // execution (still correct; just no overlap).
    static cudaStream_t s1 = 0;
    static cudaEvent_t evF[NTILE + 1];
    static cudaEvent_t evR[NTILE];
    static int inited = 0;        // 0 = not tried, 1 = overlap ok, -1 = fallback
    if (inited == 0) {
        int ok = 1;
        if (cudaStreamCreateWithFlags(&s1, cudaStreamNonBlocking) != cudaSuccess)
            ok = 0;
        if (ok) {
            for (int i = 0; i <= NTILE && ok; i++)
                if (cudaEventCreateWithFlags(&evF[i], cudaEventDisableTiming)
                    != cudaSuccess) ok = 0;
            for (int i = 0; i < NTILE && ok; i++)
                if (cudaEventCreateWithFlags(&evR[i], cudaEventDisableTiming)
                    != cudaSuccess) ok = 0;
        }
        const int p3s = (BB * ASTR + BB * 128) * (int)sizeof(float);
        cudaFuncSetAttribute(fw_rest, cudaFuncAttributeMaxDynamicSharedMemorySize,
                             p3s);
        cudaGetLastError();       // clear any sticky non-fatal error
        inited = ok ? 1 : -1;
    }
    const int p3_smem = (BB * ASTR + BB * 128) * (int)sizeof(float);  // 66560 B

    k_build_w<<<dim3(NN/32, NN/32), 256>>>(m, nw);
    k_anchors<<<NN / 256, 256>>>(nw);

    if (inited == 1) {
        // Overlapped schedule: bulk phase3 on s1, band-critical path on 0.
        fw_p12<<<64, 256>>>(0);
        cudaEventRecord(evF[0], 0);
        for (int k = 0; k < NTILE; k++) {
            cudaStreamWaitEvent(s1, evF[k], 0);
            fw_rest<<<dim3(16, 16), 256, p3_smem, s1>>>(k, k + 1);
            cudaEventRecord(evR[k], s1);
            if (k < NTILE - 1) {
                if (k > 0) cudaStreamWaitEvent(0, evR[k - 1], 0);
                fw_crit<<<64, 256>>>(k);
                fw_p12<<<64, 256>>>(k + 1);
                cudaEventRecord(evF[k + 1], 0);
            }
        }
        cudaStreamWaitEvent(0, evR[NTILE - 1], 0);
    } else {
        // Serialized fallback (R4 schedule; mk=NTILE disables masking).
        for (int k = 0; k < NTILE; k++) {
            fw_p12<<<64, 256>>>(k);
            fw_rest<<<dim3(16, 16), 256, p3_smem>>>(k, NTILE);
        }
    }

    k_gather<<<NN, 128>>>(wm, out);
    k_finalize<<<1, 256>>>(out);
    k_graph<<<dim3(NTILE, NTILE), 256>>>(sg, out);
}

// round 9
// speedup vs baseline: 1.0108x; 1.0108x over previous
#include <cuda_runtime.h>
#include <math.h>

#define NN 2048
#define AA 100
#define BB 64
#define NTILE 32           // NN / BB (FW band grid)
#define OUT_SUM (NN*AA)
#define OUT_G   (NN*AA+1)
#define ASTR 132
#define P3_SMEM ((BB*ASTR + BB*128) * (int)sizeof(float))   // 66560 B
#define PGRID 256          // persistent grid size (16x16 tile grid)

// Scratch (static __device__ arrays — no allocation)
__device__ float d_dist[NN*NN];       // 16 MB distance matrix
__device__ int   d_anchors[AA];
__device__ float d_weighted[NN*AA];
__device__ float d_xx[NN];
__device__ float d_rowsum[NN];

// Software grid-barrier state (reset by k_bar_reset each call)
__device__ unsigned int d_bar_count;
__device__ volatile unsigned int d_bar_gen;

__device__ __forceinline__ float finf() { return __int_as_float(0x7f800000); }

__global__ void k_bar_reset() { d_bar_count = 0; d_bar_gen = 0; }

// Grid-wide barrier for a co-resident grid of PGRID blocks.
// gen must increase by 1 at every successive barrier (1, 2, 3, ...).
__device__ __forceinline__ void grid_barrier(unsigned int gen) {
    __syncthreads();
    if (threadIdx.x == 0) {
        __threadfence();                      // release all prior writes
        unsigned int old = atomicAdd(&d_bar_count, 1u);
        if (old == gen * PGRID - 1u) {
            d_bar_gen = gen;                  // last arrival releases
            __threadfence();
        } else {
            while (d_bar_gen < gen) __nanosleep(64);
            __threadfence();                  // acquire
        }
    }
    __syncthreads();
}

// ---------------------------------------------------------------------------
// Build w: adj = motif * nw[i] (row-scaled), w = min(f(adj), f(adj^T)), diag 0
// ---------------------------------------------------------------------------
__global__ void __launch_bounds__(256) k_build_w(const float* __restrict__ m,
                                                 const float* __restrict__ nw) {
    __shared__ float sT[32][33];
    int bi = blockIdx.y, bj = blockIdx.x;
    int tx = threadIdx.x & 31;
    int ty = threadIdx.x >> 5;
    #pragma unroll
    for (int rr = ty; rr < 32; rr += 8)
        sT[rr][tx] = m[(bj*32 + rr)*NN + bi*32 + tx];
    __syncthreads();
    #pragma unroll
    for (int rr = ty; rr < 32; rr += 8) {
        int i = bi*32 + rr;
        int j = bj*32 + tx;
        float a = m[i*NN + j] * nw[i];
        float b = sT[tx][rr] * nw[j];
        float wa = a > 0.f ? a : finf();
        float wb = b > 0.f ? b : finf();
        float w = fminf(wa, wb);
        if (i == j) w = 0.f;
        d_dist[i*NN + j] = w;
    }
}

// ---------------------------------------------------------------------------
// Phase A body (p12, band k): close pivot (k,k) in smem, then bid<32 updates
// row panel (k,o), bid in [32,64) updates col panel (o,k).
// ---------------------------------------------------------------------------
__device__ __forceinline__ void p12_body(int k, int bid, int tid,
                                         float* Ps /*[64][68]*/,
                                         float* B1 /*[64][68]*/) {
    const int kB = k * BB;
    const int pbase = kB * NN + kB;

    #pragma unroll
    for (int e = tid; e < BB * BB; e += 256)
        Ps[(e >> 6) * 68 + (e & 63)] = d_dist[pbase + (e >> 6) * NN + (e & 63)];
    __syncthreads();

    int r  = tid >> 2;
    int c0 = (tid & 3) << 4;
    float cur[16];
    #pragma unroll
    for (int x = 0; x < 16; x++) cur[x] = Ps[r * 68 + c0 + x];

    for (int kk = 0; kk < BB; kk++) {
        float a = Ps[r * 68 + kk];
        float bv[16];
        #pragma unroll
        for (int q = 0; q < 4; q++) {
            float4 v = *(const float4*)&Ps[kk * 68 + c0 + q * 4];
            bv[q*4+0] = v.x; bv[q*4+1] = v.y; bv[q*4+2] = v.z; bv[q*4+3] = v.w;
        }
        #pragma unroll
        for (int x = 0; x < 16; x++)
            cur[x] = fminf(cur[x], a + bv[x]);
        #pragma unroll
        for (int q = 0; q < 4; q++)
            *(float4*)&Ps[r * 68 + c0 + q * 4] =
                make_float4(cur[q*4+0], cur[q*4+1], cur[q*4+2], cur[q*4+3]);
        __syncthreads();
    }
    // Ps = P*, cur = this thread's 1x16 row segment of P*.

    int o = bid & 31;
    int tx = tid & 15, ty = tid >> 4;
    int rr0 = ty << 2, cc0 = tx << 2;
    float acc[4][4];
    #pragma unroll
    for (int a = 0; a < 4; a++)
        #pragma unroll
        for (int b = 0; b < 4; b++) acc[a][b] = finf();

    if (bid < 32) {
        #pragma unroll
        for (int x = 0; x < 16; x++) B1[(c0 + x) * 68 + r] = cur[x];  // P*^T
        #pragma unroll
        for (int e = tid; e < BB * BB; e += 256)
            Ps[(e >> 6) * 68 + (e & 63)] =
                d_dist[(kB + (e >> 6)) * NN + o * BB + (e & 63)];
        __syncthreads();
        #pragma unroll 4
        for (int p = 0; p < BB; p++) {
            float4 a4 = *(const float4*)&B1[p * 68 + rr0];
            float4 b4 = *(const float4*)&Ps[p * 68 + cc0];
            float av[4] = {a4.x, a4.y, a4.z, a4.w};
            float bv[4] = {b4.x, b4.y, b4.z, b4.w};
            #pragma unroll
            for (int a = 0; a < 4; a++)
                #pragma unroll
                for (int b = 0; b < 4; b++)
                    acc[a][b] = fminf(acc[a][b], av[a] + bv[b]);
        }
        #pragma unroll
        for (int a = 0; a < 4; a++)
            *(float4*)&d_dist[(kB + rr0 + a) * NN + o * BB + cc0] =
                make_float4(acc[a][0], acc[a][1], acc[a][2], acc[a][3]);
    } else {
        #pragma unroll
        for (int e = tid; e < BB * BB; e += 256) {
            int ii = e >> 6, p = e & 63;
            B1[p * 68 + ii] = d_dist[(o * BB + ii) * NN + kB + p];
        }
        __syncthreads();
        #pragma unroll 4
        for (int p = 0; p < BB; p++) {
            float4 a4 = *(const float4*)&B1[p * 68 + rr0];
            float4 b4 = *(const float4*)&Ps[p * 68 + cc0];
            float av[4] = {a4.x, a4.y, a4.z, a4.w};
            float bv[4] = {b4.x, b4.y, b4.z, b4.w};
            #pragma unroll
            for (int a = 0; a < 4; a++)
                #pragma unroll
                for (int b = 0; b < 4; b++)
                    acc[a][b] = fminf(acc[a][b], av[a] + bv[b]);
        }
        #pragma unroll
        for (int a = 0; a < 4; a++)
            *(float4*)&d_dist[(o * BB + rr0 + a) * NN + kB + cc0] =
                make_float4(acc[a][0], acc[a][1], acc[a][2], acc[a][3]);
    }
}

// ---------------------------------------------------------------------------
// Phase B body (bulk phase3): 128x128 C tile, K=64 panel, 8x8 microtile.
// ---------------------------------------------------------------------------
__device__ __forceinline__ void rest_body(int k, int bx, int by, int tid,
                                          float* AsT /*[64][ASTR]*/,
                                          float* Bs  /*[64][128]*/) {
    const int kB = k * BB;

    #pragma unroll
    for (int e = tid; e < 128 * 64; e += 256) {
        int rr = e >> 6, p = e & 63;
        AsT[p * ASTR + rr] = d_dist[(by * 128 + rr) * NN + kB + p];
    }
    #pragma unroll
    for (int e = tid; e < 64 * 128; e += 256) {
        int p = e >> 7, j = e & 127;
        Bs[p * 128 + j] = d_dist[(kB + p) * NN + bx * 128 + j];
    }

    int tx = tid & 15, ty = tid >> 4;
    int r0 = ty << 3, c0 = tx << 3;
    const int cbase = (by * 128 + r0) * NN + bx * 128 + c0;
    float acc[8][8];
    #pragma unroll
    for (int a = 0; a < 8; a++) {
        float4 v0 = *(const float4*)&d_dist[cbase + a * NN];
        float4 v1 = *(const float4*)&d_dist[cbase + a * NN + 4];
        acc[a][0] = v0.x; acc[a][1] = v0.y; acc[a][2] = v0.z; acc[a][3] = v0.w;
        acc[a][4] = v1.x; acc[a][5] = v1.y; acc[a][6] = v1.z; acc[a][7] = v1.w;
    }
    __syncthreads();

    #pragma unroll 4
    for (int p = 0; p < BB; p++) {
        float4 a0 = *(const float4*)&AsT[p * ASTR + r0];
        float4 a1 = *(const float4*)&AsT[p * ASTR + r0 + 4];
        float4 b0 = *(const float4*)&Bs[p * 128 + c0];
        float4 b1 = *(const float4*)&Bs[p * 128 + c0 + 4];
        float av[8] = {a0.x, a0.y, a0.z, a0.w, a1.x, a1.y, a1.z, a1.w};
        float bv[8] = {b0.x, b0.y, b0.z, b0.w, b1.x, b1.y, b1.z, b1.w};
        #pragma unroll
        for (int a = 0; a < 8; a++)
            #pragma unroll
            for (int b = 0; b < 8; b++)
                acc[a][b] = fminf(acc[a][b], av[a] + bv[b]);
    }

    #pragma unroll
    for (int a = 0; a < 8; a++) {
        *(float4*)&d_dist[cbase + a * NN] =
            make_float4(acc[a][0], acc[a][1], acc[a][2], acc[a][3]);
        *(float4*)&d_dist[cbase + a * NN + 4] =
            make_float4(acc[a][4], acc[a][5], acc[a][6], acc[a][7]);
    }
}

// ---------------------------------------------------------------------------
// Persistent FW with software grid barrier: all 32 rounds in one PLAIN
// launch. PGRID=256 blocks, all co-resident (checked host-side: >=2
// blocks/SM and 2*SMs >= 256 before choosing this path).
// ---------------------------------------------------------------------------
__global__ void __launch_bounds__(256, 2) fw_persist_sw() {
    extern __shared__ float sm[];
    int tid = threadIdx.x;
    int bid = blockIdx.x;
    int bx = bid & 15, by = bid >> 4;

    unsigned int gen = 0;
    for (int k = 0; k < NTILE; k++) {
        if (bid < 64)
            p12_body(k, bid, tid, sm, sm + 64 * 68);
        grid_barrier(++gen);
        rest_body(k, bx, by, tid, sm, sm + BB * ASTR);
        grid_barrier(++gen);
    }
}

// Fallback standalone kernels (R4-proven schedule) -------------------------
__global__ void __launch_bounds__(256) fw_p12(int k) {
    __shared__ float sm[2 * 64 * 68];
    p12_body(k, blockIdx.x, threadIdx.x, sm, sm + 64 * 68);
}
__global__ void __launch_bounds__(256, 2) fw_rest(int k) {
    extern __shared__ float sm[];
    rest_body(k, blockIdx.x, blockIdx.y, threadIdx.x, sm, sm + BB * ASTR);
}

// ---------------------------------------------------------------------------
// Anchors: exact stable argsort(-nw)[:100] via rank counting
// ---------------------------------------------------------------------------
__global__ void k_anchors(const float* __restrict__ nw) {
    __shared__ float s[NN];
    int tid = threadIdx.x;
    for (int e = tid; e < NN; e += 256) s[e] = nw[e];
    __syncthreads();
    int i = blockIdx.x * 256 + tid;
    float v = s[i];
    int rank = 0;
    for (int j = 0; j < NN; j++) {
        float u = s[j];
        rank += (u > v) || (u == v && j < i);
    }
    if (rank < AA) d_anchors[rank] = i;
}

// ---------------------------------------------------------------------------
__global__ void k_gather(const float* __restrict__ wm, float* __restrict__ out) {
    __shared__ int anc[AA];
    __shared__ float r1[128], r2[128];
    int i = blockIdx.x, tid = threadIdx.x;
    if (tid < AA) anc[tid] = d_anchors[tid];
    __syncthreads();
    float cv = 0.f, wsq = 0.f;
    if (tid < AA) {
        float v = d_dist[i * NN + anc[tid]];
        if (v > 3.0e38f) v = 100.f;
        out[i * AA + tid] = v;
        float w = wm[i * AA + tid] * v;
        d_weighted[i * AA + tid] = w;
        cv = v; wsq = w * w;
    }
    r1[tid] = cv; r2[tid] = wsq;
    __syncthreads();
    for (int st = 64; st > 0; st >>= 1) {
        if (tid < st) { r1[tid] += r1[tid + st]; r2[tid] += r2[tid + st]; }
        __syncthreads();
    }
    if (tid == 0) { d_rowsum[i] = r1[0]; d_xx[i] = r2[0]; }
}

__global__ void k_finalize(float* __restrict__ out) {
    __shared__ float red[256];
    int tid = threadIdx.x;
    float s = 0.f;
    for (int e = tid; e < NN; e += 256) s += d_rowsum[e];
    red[tid] = s;
    __syncthreads();
    for (int st = 128; st > 0; st >>= 1) {
        if (tid < st) red[tid] += red[tid + st];
        __syncthreads();
    }
    if (tid == 0) out[OUT_SUM] = (red[0] - 100.f * NN) / ((float)NN * AA);
}

// ---------------------------------------------------------------------------
__global__ void __launch_bounds__(256) k_graph(const float* __restrict__ sigma_p,
                                               float* __restrict__ out) {
    __shared__ float WiT[32][BB + 4];
    __shared__ float WjT[32][BB + 4];
    int bx = blockIdx.x, by = blockIdx.y;
    int tid = threadIdx.x, tx = tid & 15, ty = tid >> 4;
    int r0 = ty << 2, c0 = tx << 2;
    float acc[4][4] = {};
    for (int k0 = 0; k0 < 128; k0 += 32) {
        for (int e = tid; e < BB * 32; e += 256) {
            int rr = e >> 5, kc = e & 31;
            int kg = k0 + kc;
            float wi = 0.f, wj = 0.f;
            if (kg < AA) {
                wi = d_weighted[(by * BB + rr) * AA + kg];
                wj = d_weighted[(bx * BB + rr) * AA + kg];
            }
            WiT[kc][rr] = wi; WjT[kc][rr] = wj;
        }
        __syncthreads();
        #pragma unroll
        for (int kc = 0; kc < 32; kc++) {
            float4 a4 = *(const float4*)&WiT[kc][r0];
            float4 b4 = *(const float4*)&WjT[kc][c0];
            float av[4] = {a4.x, a4.y, a4.z, a4.w};
            float bv[4] = {b4.x, b4.y, b4.z, b4.w};
            #pragma unroll
            for (int a = 0; a < 4; a++)
                #pragma unroll
                for (int b = 0; b < 4; b++)
                    acc[a][b] += av[a] * bv[b];
        }
        __syncthreads();
    }
    float sg = *sigma_p;
    float inv2 = 0.5f / (sg * sg);
    float xi[4], xj[4];
    #pragma unroll
    for (int a = 0; a < 4; a++) xi[a] = d_xx[by * BB + r0 + a];
    #pragma unroll
    for (int b = 0; b < 4; b++) xj[b] = d_xx[bx * BB + c0 + b];
    #pragma unroll
    for (int a = 0; a < 4; a++) {
        int i = by * BB + r0 + a;
        #pragma unroll
        for (int b = 0; b < 4; b++) {
            int j = bx * BB + c0 + b;
            float sq = xi[a] + xj[b] - 2.f * acc[a][b];
            sq = fmaxf(sq, 0.f);
            out[OUT_G + i * NN + j] = expf(-(sq * sq) * inv2);
        }
    }
}

// ---------------------------------------------------------------------------
extern "C" void kernel_launch(void* const* d_in, const int* in_sizes, int n_in,
                              void* d_out, int out_size) {
    const float* m  = (const float*)d_in[0];
    const float* nw = (const float*)d_in[1];
    const float* wm = (const float*)d_in[2];
    const float* sg = (const float*)d_in[3];
    float* out = (float*)d_out;

    // One-time decision on the first (uncaptured) correctness call: persistent
    // kernel only if all PGRID blocks are guaranteed co-resident.
    static int mode = 0;   // 0 = undecided, 1 = persistent, -1 = serial
    if (mode == 0) {
        cudaFuncSetAttribute(fw_persist_sw,
                             cudaFuncAttributeMaxDynamicSharedMemorySize, P3_SMEM);
        cudaFuncSetAttribute(fw_rest,
                             cudaFuncAttributeMaxDynamicSharedMemorySize, P3_SMEM);
        int dev = 0, nb = 0, sms = 0;
        cudaGetDevice(&dev);
        cudaOccupancyMaxActiveBlocksPerMultiprocessor(&nb, fw_persist_sw, 256,
                                                      P3_SMEM);
        cudaDeviceGetAttribute(&sms, cudaDevAttrMultiProcessorCount, dev);
        mode = (nb >= 2 && nb * sms >= PGRID) ? 1 : -1;
        cudaGetLastError();
    }

    k_build_w<<<dim3(NN/32, NN/32), 256>>>(m, nw);
    k_anchors<<<NN / 256, 256>>>(nw);

    if (mode == 1) {
        k_bar_reset<<<1, 1>>>();
        fw_persist_sw<<<PGRID, 256, P3_SMEM>>>();
    } else {
        for (int k = 0; k < NTILE; k++) {
            fw_p12<<<64, 256>>>(k);
            fw_rest<<<dim3(16, 16), 256, P3_SMEM>>>(k);
        }
    }

    k_gather<<<NN, 128>>>(wm, out);
    k_finalize<<<1, 256>>>(out);
    k_graph<<<dim3(NTILE, NTILE), 256>>>(sg, out);
}

// round 10
// speedup vs baseline: 1.0701x; 1.0587x over previous
#include <cuda_runtime.h>
#include <math.h>

#define NN 2048
#define AA 100
#define BB 64
#define NTILE 32           // NN / BB (FW band grid)
#define OUT_SUM (NN*AA)
#define OUT_G   (NN*AA+1)
#define ASTR2 260          // AsT2 row stride (floats): 16B-aligned, low-conflict
#define P3_SMEM ((BB*ASTR2 + BB*128) * (int)sizeof(float))   // 99328 B

// Scratch (static __device__ arrays — no allocation)
__device__ float d_dist[NN*NN];       // 16 MB distance matrix
__device__ int   d_anchors[AA];
__device__ float d_weighted[NN*AA];
__device__ float d_xx[NN];
__device__ float d_rowsum[NN];

__device__ __forceinline__ float finf() { return __int_as_float(0x7f800000); }

// ---------------------------------------------------------------------------
// Build w: adj = motif * nw[i] (row-scaled), w = min(f(adj), f(adj^T)), diag 0
// ---------------------------------------------------------------------------
__global__ void __launch_bounds__(256) k_build_w(const float* __restrict__ m,
                                                 const float* __restrict__ nw) {
    __shared__ float sT[32][33];
    int bi = blockIdx.y, bj = blockIdx.x;
    int tx = threadIdx.x & 31;
    int ty = threadIdx.x >> 5;
    #pragma unroll
    for (int rr = ty; rr < 32; rr += 8)
        sT[rr][tx] = m[(bj*32 + rr)*NN + bi*32 + tx];
    __syncthreads();
    #pragma unroll
    for (int rr = ty; rr < 32; rr += 8) {
        int i = bi*32 + rr;
        int j = bj*32 + tx;
        float a = m[i*NN + j] * nw[i];
        float b = sT[tx][rr] * nw[j];
        float wa = a > 0.f ? a : finf();
        float wb = b > 0.f ? b : finf();
        float w = fminf(wa, wb);
        if (i == j) w = 0.f;
        d_dist[i*NN + j] = w;
    }
}

// ---------------------------------------------------------------------------
// Fused phase1+2 (band k): all 64 blocks redundantly close pivot (k,k) in
// smem, then bid<32 updates row panel (k,o), bid>=32 col panel (o,k).
// (R4-proven version, unchanged.)
// ---------------------------------------------------------------------------
__global__ void __launch_bounds__(256) fw_p12(int k) {
    __shared__ float Ps[BB][BB + 4];
    __shared__ float B1[BB][BB + 4];
    int tid = threadIdx.x;
    const int kB = k * BB;
    const int pbase = kB * NN + kB;

    #pragma unroll
    for (int e = tid; e < BB * BB; e += 256)
        Ps[e >> 6][e & 63] = d_dist[pbase + (e >> 6) * NN + (e & 63)];
    __syncthreads();

    int r  = tid >> 2;
    int c0 = (tid & 3) << 4;
    float cur[16];
    #pragma unroll
    for (int x = 0; x < 16; x++) cur[x] = Ps[r][c0 + x];

    for (int kk = 0; kk < BB; kk++) {
        float a = Ps[r][kk];
        float bv[16];
        #pragma unroll
        for (int q = 0; q < 4; q++) {
            float4 v = *(const float4*)&Ps[kk][c0 + q * 4];
            bv[q*4+0] = v.x; bv[q*4+1] = v.y; bv[q*4+2] = v.z; bv[q*4+3] = v.w;
        }
        #pragma unroll
        for (int x = 0; x < 16; x++)
            cur[x] = fminf(cur[x], a + bv[x]);
        #pragma unroll
        for (int q = 0; q < 4; q++)
            *(float4*)&Ps[r][c0 + q * 4] =
                make_float4(cur[q*4+0], cur[q*4+1], cur[q*4+2], cur[q*4+3]);
        __syncthreads();
    }

    int bid = blockIdx.x;
    int o = bid & 31;
    int tx = tid & 15, ty = tid >> 4;
    int rr0 = ty << 2, cc0 = tx << 2;
    float acc[4][4];
    #pragma unroll
    for (int a = 0; a < 4; a++)
        #pragma unroll
        for (int b = 0; b < 4; b++) acc[a][b] = finf();

    if (bid < 32) {
        #pragma unroll
        for (int x = 0; x < 16; x++) B1[c0 + x][r] = cur[x];   // P*^T
        #pragma unroll
        for (int e = tid; e < BB * BB; e += 256)
            Ps[e >> 6][e & 63] = d_dist[(kB + (e >> 6)) * NN + o * BB + (e & 63)];
        __syncthreads();
        #pragma unroll 4
        for (int p = 0; p < BB; p++) {
            float4 a4 = *(const float4*)&B1[p][rr0];
            float4 b4 = *(const float4*)&Ps[p][cc0];
            float av[4] = {a4.x, a4.y, a4.z, a4.w};
            float bv[4] = {b4.x, b4.y, b4.z, b4.w};
            #pragma unroll
            for (int a = 0; a < 4; a++)
                #pragma unroll
                for (int b = 0; b < 4; b++)
                    acc[a][b] = fminf(acc[a][b], av[a] + bv[b]);
        }
        #pragma unroll
        for (int a = 0; a < 4; a++)
            *(float4*)&d_dist[(kB + rr0 + a) * NN + o * BB + cc0] =
                make_float4(acc[a][0], acc[a][1], acc[a][2], acc[a][3]);
    } else {
        #pragma unroll
        for (int e = tid; e < BB * BB; e += 256) {
            int ii = e >> 6, p = e & 63;
            B1[p][ii] = d_dist[(o * BB + ii) * NN + kB + p];
        }
        __syncthreads();
        #pragma unroll 4
        for (int p = 0; p < BB; p++) {
            float4 a4 = *(const float4*)&B1[p][rr0];
            float4 b4 = *(const float4*)&Ps[p][cc0];
            float av[4] = {a4.x, a4.y, a4.z, a4.w};
            float bv[4] = {b4.x, b4.y, b4.z, b4.w};
            #pragma unroll
            for (int a = 0; a < 4; a++)
                #pragma unroll
                for (int b = 0; b < 4; b++)
                    acc[a][b] = fminf(acc[a][b], av[a] + bv[b]);
        }
        #pragma unroll
        for (int a = 0; a < 4; a++)
            *(float4*)&d_dist[(o * BB + rr0 + a) * NN + kB + cc0] =
                make_float4(acc[a][0], acc[a][1], acc[a][2], acc[a][3]);
    }
}

// ---------------------------------------------------------------------------
// Bulk phase3: 128x128 C tile, K=64 panel, 8x8 microtile, packed f32x2 adds.
// A panel stored in smem as duplicated pairs: AsT2[p][2i]=(a_i,a_i), so each
// LDS.128 yields two ready f32x2 operands (no pack MOVs). B pairs come packed
// naturally. Inner op: t = add.rn.f32x2(a_dup, b_pair); acc = fminf(acc, t.lo/hi).
// Bit-identical to scalar FADD+FMNMX.
// ---------------------------------------------------------------------------
__global__ void __launch_bounds__(256, 2) fw_rest(int k) {
    extern __shared__ float sm[];
    float* AsT2 = sm;                    // [64][ASTR2]  dup pairs, AsT2[p][2i]
    float* Bs   = sm + BB * ASTR2;       // [64][128]    Bs[p][j]
    int tid = threadIdx.x;
    int bx = blockIdx.x, by = blockIdx.y;
    const int kB = k * BB;

    // A: 128 rows x 64 cols -> transposed + duplicated pairs
    #pragma unroll
    for (int e = tid; e < 128 * 64; e += 256) {
        int rr = e >> 6, p = e & 63;
        float v = d_dist[(by * 128 + rr) * NN + kB + p];
        *(float2*)&AsT2[p * ASTR2 + 2 * rr] = make_float2(v, v);
    }
    // B: 64 rows x 128 cols
    #pragma unroll
    for (int e = tid; e < 64 * 128; e += 256) {
        int p = e >> 7, j = e & 127;
        Bs[p * 128 + j] = d_dist[(kB + p) * NN + bx * 128 + j];
    }

    int tx = tid & 15, ty = tid >> 4;
    int r0 = ty << 3, c0 = tx << 3;
    const int cbase = (by * 128 + r0) * NN + bx * 128 + c0;
    float acc[8][8];
    #pragma unroll
    for (int a = 0; a < 8; a++) {
        float4 v0 = *(const float4*)&d_dist[cbase + a * NN];
        float4 v1 = *(const float4*)&d_dist[cbase + a * NN + 4];
        acc[a][0] = v0.x; acc[a][1] = v0.y; acc[a][2] = v0.z; acc[a][3] = v0.w;
        acc[a][4] = v1.x; acc[a][5] = v1.y; acc[a][6] = v1.z; acc[a][7] = v1.w;
    }
    __syncthreads();

    const float* aRowBase = &AsT2[2 * r0];
    const float* bRowBase = &Bs[c0];

    #pragma unroll 2
    for (int p = 0; p < BB; p++) {
        const float* aRow = aRowBase + p * ASTR2;
        const float* bRow = bRowBase + p * 128;
        ulonglong2 aq01 = *(const ulonglong2*)(aRow);       // (a0,a0),(a1,a1)
        ulonglong2 aq23 = *(const ulonglong2*)(aRow + 4);
        ulonglong2 aq45 = *(const ulonglong2*)(aRow + 8);
        ulonglong2 aq67 = *(const ulonglong2*)(aRow + 12);
        ulonglong2 bq03 = *(const ulonglong2*)(bRow);       // (b0,b1),(b2,b3)
        ulonglong2 bq47 = *(const ulonglong2*)(bRow + 4);
        unsigned long long aq[8] = {aq01.x, aq01.y, aq23.x, aq23.y,
                                    aq45.x, aq45.y, aq67.x, aq67.y};
        unsigned long long bq[4] = {bq03.x, bq03.y, bq47.x, bq47.y};
        #pragma unroll
        for (int a = 0; a < 8; a++) {
            #pragma unroll
            for (int b2 = 0; b2 < 4; b2++) {
                unsigned long long t;
                asm("add.rn.f32x2 %0, %1, %2;" : "=l"(t)
                    : "l"(aq[a]), "l"(bq[b2]));
                float lo, hi;
                asm("mov.b64 {%0, %1}, %2;" : "=f"(lo), "=f"(hi) : "l"(t));
                acc[a][2*b2]     = fminf(acc[a][2*b2],     lo);
                acc[a][2*b2 + 1] = fminf(acc[a][2*b2 + 1], hi);
            }
        }
    }

    #pragma unroll
    for (int a = 0; a < 8; a++) {
        *(float4*)&d_dist[cbase + a * NN] =
            make_float4(acc[a][0], acc[a][1], acc[a][2], acc[a][3]);
        *(float4*)&d_dist[cbase + a * NN + 4] =
            make_float4(acc[a][4], acc[a][5], acc[a][6], acc[a][7]);
    }
}

// ---------------------------------------------------------------------------
// Anchors: exact stable argsort(-nw)[:100] via rank counting
// ---------------------------------------------------------------------------
__global__ void k_anchors(const float* __restrict__ nw) {
    __shared__ float s[NN];
    int tid = threadIdx.x;
    for (int e = tid; e < NN; e += 256) s[e] = nw[e];
    __syncthreads();
    int i = blockIdx.x * 256 + tid;
    float v = s[i];
    int rank = 0;
    for (int j = 0; j < NN; j++) {
        float u = s[j];
        rank += (u > v) || (u == v && j < i);
    }
    if (rank < AA) d_anchors[rank] = i;
}

// ---------------------------------------------------------------------------
__global__ void k_gather(const float* __restrict__ wm, float* __restrict__ out) {
    __shared__ int anc[AA];
    __shared__ float r1[128], r2[128];
    int i = blockIdx.x, tid = threadIdx.x;
    if (tid < AA) anc[tid] = d_anchors[tid];
    __syncthreads();
    float cv = 0.f, wsq = 0.f;
    if (tid < AA) {
        float v = d_dist[i * NN + anc[tid]];
        if (v > 3.0e38f) v = 100.f;
        out[i * AA + tid] = v;
        float w = wm[i * AA + tid] * v;
        d_weighted[i * AA + tid] = w;
        cv = v; wsq = w * w;
    }
    r1[tid] = cv; r2[tid] = wsq;
    __syncthreads();
    for (int st = 64; st > 0; st >>= 1) {
        if (tid < st) { r1[tid] += r1[tid + st]; r2[tid] += r2[tid + st]; }
        __syncthreads();
    }
    if (tid == 0) { d_rowsum[i] = r1[0]; d_xx[i] = r2[0]; }
}

__global__ void k_finalize(float* __restrict__ out) {
    __shared__ float red[256];
    int tid = threadIdx.x;
    float s = 0.f;
    for (int e = tid; e < NN; e += 256) s += d_rowsum[e];
    red[tid] = s;
    __syncthreads();
    for (int st = 128; st > 0; st >>= 1) {
        if (tid < st) red[tid] += red[tid + st];
        __syncthreads();
    }
    if (tid == 0) out[OUT_SUM] = (red[0] - 100.f * NN) / ((float)NN * AA);
}

// ---------------------------------------------------------------------------
__global__ void __launch_bounds__(256) k_graph(const float* __restrict__ sigma_p,
                                               float* __restrict__ out) {
    __shared__ float WiT[32][BB + 4];
    __shared__ float WjT[32][BB + 4];
    int bx = blockIdx.x, by = blockIdx.y;
    int tid = threadIdx.x, tx = tid & 15, ty = tid >> 4;
    int r0 = ty << 2, c0 = tx << 2;
    float acc[4][4] = {};
    for (int k0 = 0; k0 < 128; k0 += 32) {
        for (int e = tid; e < BB * 32; e += 256) {
            int rr = e >> 5, kc = e & 31;
            int kg = k0 + kc;
            float wi = 0.f, wj = 0.f;
            if (kg < AA) {
                wi = d_weighted[(by * BB + rr) * AA + kg];
                wj = d_weighted[(bx * BB + rr) * AA + kg];
            }
            WiT[kc][rr] = wi; WjT[kc][rr] = wj;
        }
        __syncthreads();
        #pragma unroll
        for (int kc = 0; kc < 32; kc++) {
            float4 a4 = *(const float4*)&WiT[kc][r0];
            float4 b4 = *(const float4*)&WjT[kc][c0];
            float av[4] = {a4.x, a4.y, a4.z, a4.w};
            float bv[4] = {b4.x, b4.y, b4.z, b4.w};
            #pragma unroll
            for (int a = 0; a < 4; a++)
                #pragma unroll
                for (int b = 0; b < 4; b++)
                    acc[a][b] += av[a] * bv[b];
        }
        __syncthreads();
    }
    float sg = *sigma_p;
    float inv2 = 0.5f / (sg * sg);
    float xi[4], xj[4];
    #pragma unroll
    for (int a = 0; a < 4; a++) xi[a] = d_xx[by * BB + r0 + a];
    #pragma unroll
    for (int b = 0; b < 4; b++) xj[b] = d_xx[bx * BB + c0 + b];
    #pragma unroll
    for (int a = 0; a < 4; a++) {
        int i = by * BB + r0 + a;
        #pragma unroll
        for (int b = 0; b < 4; b++) {
            int j = bx * BB + c0 + b;
            float sq = xi[a] + xj[b] - 2.f * acc[a][b];
            sq = fmaxf(sq, 0.f);
            out[OUT_G + i * NN + j] = expf(-(sq * sq) * inv2);
        }
    }
}

// ---------------------------------------------------------------------------
extern "C" void kernel_launch(void* const* d_in, const int* in_sizes, int n_in,
                              void* d_out, int out_size) {
    const float* m  = (const float*)d_in[0];
    const float* nw = (const float*)d_in[1];
    const float* wm = (const float*)d_in[2];
    const float* sg = (const float*)d_in[3];
    float* out = (float*)d_out;

    static int inited = 0;
    if (!inited) {
        cudaFuncSetAttribute(fw_rest,
                             cudaFuncAttributeMaxDynamicSharedMemorySize, P3_SMEM);
        inited = 1;
    }

    k_build_w<<<dim3(NN/32, NN/32), 256>>>(m, nw);
    k_anchors<<<NN / 256, 256>>>(nw);

    for (int k = 0; k < NTILE; k++) {
        fw_p12<<<64, 256>>>(k);
        fw_rest<<<dim3(16, 16), 256, P3_SMEM>>>(k);
    }

    k_gather<<<NN, 128>>>(wm, out);
    k_finalize<<<1, 256>>>(out);
    k_graph<<<dim3(NTILE, NTILE), 256>>>(sg, out);
}

// round 11
// speedup vs baseline: 1.0882x; 1.0169x over previous
#include <cuda_runtime.h>
#include <math.h>

#define NN 2048
#define AA 100
#define BB 64
#define NTILE 32           // NN / BB (FW band grid)
#define OUT_SUM (NN*AA)
#define OUT_G   (NN*AA+1)
#define ASTR 132
#define P3_SMEM ((BB*ASTR + BB*68) * (int)sizeof(float))   // 51200 B

// Scratch (static __device__ arrays — no allocation)
__device__ float d_dist[NN*NN];       // 16 MB distance matrix
__device__ int   d_anchors[AA];
__device__ float d_weighted[NN*AA];
__device__ float d_xx[NN];
__device__ float d_rowsum[NN];

__device__ __forceinline__ float finf() { return __int_as_float(0x7f800000); }

// ---------------------------------------------------------------------------
// Build w: adj = motif * nw[i] (row-scaled), w = min(f(adj), f(adj^T)), diag 0
// ---------------------------------------------------------------------------
__global__ void __launch_bounds__(256) k_build_w(const float* __restrict__ m,
                                                 const float* __restrict__ nw) {
    __shared__ float sT[32][33];
    int bi = blockIdx.y, bj = blockIdx.x;
    int tx = threadIdx.x & 31;
    int ty = threadIdx.x >> 5;
    #pragma unroll
    for (int rr = ty; rr < 32; rr += 8)
        sT[rr][tx] = m[(bj*32 + rr)*NN + bi*32 + tx];
    __syncthreads();
    #pragma unroll
    for (int rr = ty; rr < 32; rr += 8) {
        int i = bi*32 + rr;
        int j = bj*32 + tx;
        float a = m[i*NN + j] * nw[i];
        float b = sT[tx][rr] * nw[j];
        float wa = a > 0.f ? a : finf();
        float wb = b > 0.f ? b : finf();
        float w = fminf(wa, wb);
        if (i == j) w = 0.f;
        d_dist[i*NN + j] = w;
    }
}

// ---------------------------------------------------------------------------
// Fused phase1+2 (band k): all 64 blocks redundantly close pivot (k,k) in
// smem, then bid<32 updates row panel (k,o), bid>=32 col panel (o,k).
// (R4-proven version, unchanged.)
// ---------------------------------------------------------------------------
__global__ void __launch_bounds__(256) fw_p12(int k) {
    __shared__ float Ps[BB][BB + 4];
    __shared__ float B1[BB][BB + 4];
    int tid = threadIdx.x;
    const int kB = k * BB;
    const int pbase = kB * NN + kB;

    #pragma unroll
    for (int e = tid; e < BB * BB; e += 256)
        Ps[e >> 6][e & 63] = d_dist[pbase + (e >> 6) * NN + (e & 63)];
    __syncthreads();

    int r  = tid >> 2;
    int c0 = (tid & 3) << 4;
    float cur[16];
    #pragma unroll
    for (int x = 0; x < 16; x++) cur[x] = Ps[r][c0 + x];

    for (int kk = 0; kk < BB; kk++) {
        float a = Ps[r][kk];
        float bv[16];
        #pragma unroll
        for (int q = 0; q < 4; q++) {
            float4 v = *(const float4*)&Ps[kk][c0 + q * 4];
            bv[q*4+0] = v.x; bv[q*4+1] = v.y; bv[q*4+2] = v.z; bv[q*4+3] = v.w;
        }
        #pragma unroll
        for (int x = 0; x < 16; x++)
            cur[x] = fminf(cur[x], a + bv[x]);
        #pragma unroll
        for (int q = 0; q < 4; q++)
            *(float4*)&Ps[r][c0 + q * 4] =
                make_float4(cur[q*4+0], cur[q*4+1], cur[q*4+2], cur[q*4+3]);
        __syncthreads();
    }

    int bid = blockIdx.x;
    int o = bid & 31;
    int tx = tid & 15, ty = tid >> 4;
    int rr0 = ty << 2, cc0 = tx << 2;
    float acc[4][4];
    #pragma unroll
    for (int a = 0; a < 4; a++)
        #pragma unroll
        for (int b = 0; b < 4; b++) acc[a][b] = finf();

    if (bid < 32) {
        #pragma unroll
        for (int x = 0; x < 16; x++) B1[c0 + x][r] = cur[x];   // P*^T
        #pragma unroll
        for (int e = tid; e < BB * BB; e += 256)
            Ps[e >> 6][e & 63] = d_dist[(kB + (e >> 6)) * NN + o * BB + (e & 63)];
        __syncthreads();
        #pragma unroll 4
        for (int p = 0; p < BB; p++) {
            float4 a4 = *(const float4*)&B1[p][rr0];
            float4 b4 = *(const float4*)&Ps[p][cc0];
            float av[4] = {a4.x, a4.y, a4.z, a4.w};
            float bv[4] = {b4.x, b4.y, b4.z, b4.w};
            #pragma unroll
            for (int a = 0; a < 4; a++)
                #pragma unroll
                for (int b = 0; b < 4; b++)
                    acc[a][b] = fminf(acc[a][b], av[a] + bv[b]);
        }
        #pragma unroll
        for (int a = 0; a < 4; a++)
            *(float4*)&d_dist[(kB + rr0 + a) * NN + o * BB + cc0] =
                make_float4(acc[a][0], acc[a][1], acc[a][2], acc[a][3]);
    } else {
        #pragma unroll
        for (int e = tid; e < BB * BB; e += 256) {
            int ii = e >> 6, p = e & 63;
            B1[p][ii] = d_dist[(o * BB + ii) * NN + kB + p];
        }
        __syncthreads();
        #pragma unroll 4
        for (int p = 0; p < BB; p++) {
            float4 a4 = *(const float4*)&B1[p][rr0];
            float4 b4 = *(const float4*)&Ps[p][cc0];
            float av[4] = {a4.x, a4.y, a4.z, a4.w};
            float bv[4] = {b4.x, b4.y, b4.z, b4.w};
            #pragma unroll
            for (int a = 0; a < 4; a++)
                #pragma unroll
                for (int b = 0; b < 4; b++)
                    acc[a][b] = fminf(acc[a][b], av[a] + bv[b]);
        }
        #pragma unroll
        for (int a = 0; a < 4; a++)
            *(float4*)&d_dist[(o * BB + rr0 + a) * NN + kB + cc0] =
                make_float4(acc[a][0], acc[a][1], acc[a][2], acc[a][3]);
    }
}

// ---------------------------------------------------------------------------
// Bulk phase3: 128x64 C tiles (grid 32x16 = 512 blocks), K=64 panel,
// 8x4 microtile per thread, <=64 regs -> 4 blocks/SM (32 warps) for latency
// hiding. C = min(C, A(:,k) (+,min) B(k,:)). Scalar FADD+FMNMX.
// ---------------------------------------------------------------------------
__global__ void __launch_bounds__(256, 4) fw_rest(int k) {
    extern __shared__ float sm[];
    float* AsT = sm;                    // [64][ASTR]  AsT[p][i]
    float* Bs  = sm + BB * ASTR;        // [64][68]    Bs[p][j]
    int tid = threadIdx.x;
    int bx = blockIdx.x, by = blockIdx.y;     // bx: 64-col tile, by: 128-row tile
    const int kB = k * BB;

    // A: 128 rows x 64 cols, stored transposed
    #pragma unroll
    for (int e = tid; e < 128 * 64; e += 256) {
        int rr = e >> 6, p = e & 63;
        AsT[p * ASTR + rr] = d_dist[(by * 128 + rr) * NN + kB + p];
    }
    // B: 64 rows x 64 cols
    #pragma unroll
    for (int e = tid; e < 64 * 64; e += 256) {
        int p = e >> 6, j = e & 63;
        Bs[p * 68 + j] = d_dist[(kB + p) * NN + bx * 64 + j];
    }

    int tx = tid & 15, ty = tid >> 4;
    int r0 = ty << 3, c0 = tx << 2;
    const int cbase = (by * 128 + r0) * NN + bx * 64 + c0;
    float acc[8][4];
    #pragma unroll
    for (int a = 0; a < 8; a++) {
        float4 v = *(const float4*)&d_dist[cbase + a * NN];
        acc[a][0] = v.x; acc[a][1] = v.y; acc[a][2] = v.z; acc[a][3] = v.w;
    }
    __syncthreads();

    #pragma unroll 4
    for (int p = 0; p < BB; p++) {
        float4 a0 = *(const float4*)&AsT[p * ASTR + r0];
        float4 a1 = *(const float4*)&AsT[p * ASTR + r0 + 4];
        float4 b0 = *(const float4*)&Bs[p * 68 + c0];
        float av[8] = {a0.x, a0.y, a0.z, a0.w, a1.x, a1.y, a1.z, a1.w};
        float bv[4] = {b0.x, b0.y, b0.z, b0.w};
        #pragma unroll
        for (int a = 0; a < 8; a++)
            #pragma unroll
            for (int b = 0; b < 4; b++)
                acc[a][b] = fminf(acc[a][b], av[a] + bv[b]);
    }

    #pragma unroll
    for (int a = 0; a < 8; a++)
        *(float4*)&d_dist[cbase + a * NN] =
            make_float4(acc[a][0], acc[a][1], acc[a][2], acc[a][3]);
}

// ---------------------------------------------------------------------------
// Anchors: exact stable argsort(-nw)[:100] via rank counting
// ---------------------------------------------------------------------------
__global__ void k_anchors(const float* __restrict__ nw) {
    __shared__ float s[NN];
    int tid = threadIdx.x;
    for (int e = tid; e < NN; e += 256) s[e] = nw[e];
    __syncthreads();
    int i = blockIdx.x * 256 + tid;
    float v = s[i];
    int rank = 0;
    for (int j = 0; j < NN; j++) {
        float u = s[j];
        rank += (u > v) || (u == v && j < i);
    }
    if (rank < AA) d_anchors[rank] = i;
}

// ---------------------------------------------------------------------------
__global__ void k_gather(const float* __restrict__ wm, float* __restrict__ out) {
    __shared__ int anc[AA];
    __shared__ float r1[128], r2[128];
    int i = blockIdx.x, tid = threadIdx.x;
    if (tid < AA) anc[tid] = d_anchors[tid];
    __syncthreads();
    float cv = 0.f, wsq = 0.f;
    if (tid < AA) {
        float v = d_dist[i * NN + anc[tid]];
        if (v > 3.0e38f) v = 100.f;
        out[i * AA + tid] = v;
        float w = wm[i * AA + tid] * v;
        d_weighted[i * AA + tid] = w;
        cv = v; wsq = w * w;
    }
    r1[tid] = cv; r2[tid] = wsq;
    __syncthreads();
    for (int st = 64; st > 0; st >>= 1) {
        if (tid < st) { r1[tid] += r1[tid + st]; r2[tid] += r2[tid + st]; }
        __syncthreads();
    }
    if (tid == 0) { d_rowsum[i] = r1[0]; d_xx[i] = r2[0]; }
}

__global__ void k_finalize(float* __restrict__ out) {
    __shared__ float red[256];
    int tid = threadIdx.x;
    float s = 0.f;
    for (int e = tid; e < NN; e += 256) s += d_rowsum[e];
    red[tid] = s;
    __syncthreads();
    for (int st = 128; st > 0; st >>= 1) {
        if (tid < st) red[tid] += red[tid + st];
        __syncthreads();
    }
    if (tid == 0) out[OUT_SUM] = (red[0] - 100.f * NN) / ((float)NN * AA);
}

// ---------------------------------------------------------------------------
__global__ void __launch_bounds__(256) k_graph(const float* __restrict__ sigma_p,
                                               float* __restrict__ out) {
    __shared__ float WiT[32][BB + 4];
    __shared__ float WjT[32][BB + 4];
    int bx = blockIdx.x, by = blockIdx.y;
    int tid = threadIdx.x, tx = tid & 15, ty = tid >> 4;
    int r0 = ty << 2, c0 = tx << 2;
    float acc[4][4] = {};
    for (int k0 = 0; k0 < 128; k0 += 32) {
        for (int e = tid; e < BB * 32; e += 256) {
            int rr = e >> 5, kc = e & 31;
            int kg = k0 + kc;
            float wi = 0.f, wj = 0.f;
            if (kg < AA) {
                wi = d_weighted[(by * BB + rr) * AA + kg];
                wj = d_weighted[(bx * BB + rr) * AA + kg];
            }
            WiT[kc][rr] = wi; WjT[kc][rr] = wj;
        }
        __syncthreads();
        #pragma unroll
        for (int kc = 0; kc < 32; kc++) {
            float4 a4 = *(const float4*)&WiT[kc][r0];
            float4 b4 = *(const float4*)&WjT[kc][c0];
            float av[4] = {a4.x, a4.y, a4.z, a4.w};
            float bv[4] = {b4.x, b4.y, b4.z, b4.w};
            #pragma unroll
            for (int a = 0; a < 4; a++)
                #pragma unroll
                for (int b = 0; b < 4; b++)
                    acc[a][b] += av[a] * bv[b];
        }
        __syncthreads();
    }
    float sg = *sigma_p;
    float inv2 = 0.5f / (sg * sg);
    float xi[4], xj[4];
    #pragma unroll
    for (int a = 0; a < 4; a++) xi[a] = d_xx[by * BB + r0 + a];
    #pragma unroll
    for (int b = 0; b < 4; b++) xj[b] = d_xx[bx * BB + c0 + b];
    #pragma unroll
    for (int a = 0; a < 4; a++) {
        int i = by * BB + r0 + a;
        #pragma unroll
        for (int b = 0; b < 4; b++) {
            int j = bx * BB + c0 + b;
            float sq = xi[a] + xj[b] - 2.f * acc[a][b];
            sq = fmaxf(sq, 0.f);
            out[OUT_G + i * NN + j] = expf(-(sq * sq) * inv2);
        }
    }
}

// ---------------------------------------------------------------------------
extern "C" void kernel_launch(void* const* d_in, const int* in_sizes, int n_in,
                              void* d_out, int out_size) {
    const float* m  = (const float*)d_in[0];
    const float* nw = (const float*)d_in[1];
    const float* wm = (const float*)d_in[2];
    const float* sg = (const float*)d_in[3];
    float* out = (float*)d_out;

    static int inited = 0;
    if (!inited) {
        cudaFuncSetAttribute(fw_rest,
                             cudaFuncAttributeMaxDynamicSharedMemorySize, P3_SMEM);
        inited = 1;
    }

    k_build_w<<<dim3(NN/32, NN/32), 256>>>(m, nw);
    k_anchors<<<NN / 256, 256>>>(nw);

    for (int k = 0; k < NTILE; k++) {
        fw_p12<<<64, 256>>>(k);
        fw_rest<<<dim3(32, 16), 256, P3_SMEM>>>(k);
    }

    k_gather<<<NN, 128>>>(wm, out);
    k_finalize<<<1, 256>>>(out);
    k_graph<<<dim3(NTILE, NTILE), 256>>>(sg, out);
}